// round 7
// baseline (speedup 1.0000x reference)
#include <cuda_runtime.h>
#include <cstdint>

// Fixed shapes: B=4, C=3, Z=64, H=192, W=192
#define BDIM 4
#define CDIM 3
#define ZDIM 64
#define HDIM 192
#define WDIM 192
#define HW    (HDIM * WDIM)          // 36864
#define NBC   (BDIM * CDIM)          // 12
#define VOXBC (ZDIM * HW)            // 2359296 voxels per (b,c)
#define XW    (WDIM / 32)            // 6 packed words per x-row
#define WPLANE (HDIM * XW)           // 1152 words per z-plane
#define WBC   (VOXBC / 32)           // 73728 words per (b,c)

// Kernel A config
#define ABLK 288                     // blocks per (b,c)
#define ATHR 256
#define AVOX (VOXBC / ABLK)          // 8192 voxels per block
#define AF4  (AVOX / 4 / ATHR)       // 8 float4 per thread

// Kernel B config (fused stencil + finalize)
#define YT2  48
#define NYC2 (HDIM / YT2)            // 4
#define ZT2  16
#define NZC2 (ZDIM / ZT2)            // 4
#define BTHR2 384                    // 48 rows x 8 lanes; 12 warps
#define NTB  (NYC2 * NZC2)           // 16 tiles per bc
#define NBLK_B (NYC2 * NZC2 * NBC)   // 192 blocks total

__device__ uint32_t g_tsw[NBC * WBC];            // 3.5 MB bit-packed ts
__device__ float    g_partA[NBC * ABLK * 4];     // {sum_m, sum_p, sum_pm, cnt_eq}
__device__ float    g_partB[NBC * NTB];          // cnt_edge per tile
__device__ unsigned g_done = 0;                  // last-block ticket (self-resetting)

// ---------------------------------------------------------------------------
// Kernel A: stream output+masks once; reduce 4 scalars; emit bit-packed ts.
// ---------------------------------------------------------------------------
__global__ __launch_bounds__(ATHR)
void kA(const float* __restrict__ output,
        const float* __restrict__ masks,
        const float* __restrict__ thr_ptr)
{
    const int bc = blockIdx.y;
    const float thr = *thr_ptr;
    const size_t base = (size_t)bc * VOXBC + (size_t)blockIdx.x * AVOX;

    const float4* op = reinterpret_cast<const float4*>(output) + base / 4;
    const float4* mp = reinterpret_cast<const float4*>(masks)  + base / 4;
    uint32_t*     tw = g_tsw + base / 32;

    const int lane8 = threadIdx.x & 7;
    const int sh = lane8 * 4;

    float sum_p = 0.f, sum_m = 0.f, sum_pm = 0.f, cnt_eq = 0.f;

    #pragma unroll
    for (int j = 0; j < AF4; j++) {
        int idx = j * ATHR + threadIdx.x;          // coalesced float4
        float4 v = op[idx];
        float4 m = mp[idx];

        uint32_t b0 = v.x > thr;
        uint32_t b1 = v.y > thr;
        uint32_t b2 = v.z > thr;
        uint32_t b3 = v.w > thr;

        // pack 8 lanes' nibbles into one word (32 voxels)
        uint32_t w = (b0 | (b1 << 1) | (b2 << 2) | (b3 << 3)) << sh;
        w |= __shfl_xor_sync(0xFFFFFFFFu, w, 1);
        w |= __shfl_xor_sync(0xFFFFFFFFu, w, 2);
        w |= __shfl_xor_sync(0xFFFFFFFFu, w, 4);
        if (lane8 == 0) tw[idx >> 3] = w;

        sum_p  += (v.x + v.y) + (v.z + v.w);
        sum_m  += (m.x + m.y) + (m.z + m.w);
        sum_pm += v.x * m.x + v.y * m.y + v.z * m.z + v.w * m.w;

        float t0 = b0 ? 1.0f : 0.0f;
        float t1 = b1 ? 1.0f : 0.0f;
        float t2 = b2 ? 1.0f : 0.0f;
        float t3 = b3 ? 1.0f : 0.0f;
        cnt_eq += (float)((t0 == m.x) + (t1 == m.y) + (t2 == m.z) + (t3 == m.w));
    }

    __shared__ float red[ATHR / 32][4];
    #pragma unroll
    for (int o = 16; o; o >>= 1) {
        sum_m  += __shfl_xor_sync(0xFFFFFFFFu, sum_m,  o);
        sum_p  += __shfl_xor_sync(0xFFFFFFFFu, sum_p,  o);
        sum_pm += __shfl_xor_sync(0xFFFFFFFFu, sum_pm, o);
        cnt_eq += __shfl_xor_sync(0xFFFFFFFFu, cnt_eq, o);
    }
    int warp = threadIdx.x >> 5, lane = threadIdx.x & 31;
    if (lane == 0) {
        red[warp][0] = sum_m; red[warp][1] = sum_p;
        red[warp][2] = sum_pm; red[warp][3] = cnt_eq;
    }
    __syncthreads();
    if (warp == 0) {
        float v0 = lane < 8 ? red[lane][0] : 0.f;
        float v1 = lane < 8 ? red[lane][1] : 0.f;
        float v2 = lane < 8 ? red[lane][2] : 0.f;
        float v3 = lane < 8 ? red[lane][3] : 0.f;
        #pragma unroll
        for (int o = 4; o; o >>= 1) {
            v0 += __shfl_xor_sync(0xFFFFFFFFu, v0, o);
            v1 += __shfl_xor_sync(0xFFFFFFFFu, v1, o);
            v2 += __shfl_xor_sync(0xFFFFFFFFu, v2, o);
            v3 += __shfl_xor_sync(0xFFFFFFFFu, v3, o);
        }
        if (lane == 0) {
            float* dst = &g_partA[(bc * ABLK + blockIdx.x) * 4];
            dst[0] = v0; dst[1] = v1; dst[2] = v2; dst[3] = v3;
        }
    }
}

__device__ __forceinline__ float med3f(float a, float b, float c) {
    return fmaxf(fminf(a, b), fminf(fmaxf(a, b), c));
}

// ---------------------------------------------------------------------------
// Kernel B: bit-sliced Sobel edge count + last-block finalize.
// Each thread owns one (y, x-word); x-neighbor bits via shuffles.
// ---------------------------------------------------------------------------
__global__ __launch_bounds__(BTHR2)
void kB(float* __restrict__ out)
{
    const int bc  = blockIdx.z;
    const int y   = blockIdx.x * YT2 + (threadIdx.x >> 3);
    const int xw  = threadIdx.x & 7;
    const bool active = xw < XW;
    const int xwc = active ? xw : XW - 1;
    const int zlo = blockIdx.y * ZT2;

    const uint32_t* tb = g_tsw + (size_t)bc * WBC;
    const int ym = y - 1 < 0 ? 0 : y - 1;
    const int yp = y + 1 > HDIM - 1 ? HDIM - 1 : y + 1;
    const int r0 = ym * XW + xwc, r1 = y * XW + xwc, r2 = yp * XW + xwc;

    // rolling z-window of packed bits for 3 y-rows
    uint32_t o2[3], o1[3];
    {
        int zm0 = zlo - 1 < 0 ? 0 : zlo - 1;
        o2[0] = tb[zm0 * WPLANE + r0];
        o2[1] = tb[zm0 * WPLANE + r1];
        o2[2] = tb[zm0 * WPLANE + r2];
        o1[0] = tb[zlo * WPLANE + r0];
        o1[1] = tb[zlo * WPLANE + r1];
        o1[2] = tb[zlo * WPLANE + r2];
    }

    int cnt = 0;
    #pragma unroll 4
    for (int z = zlo; z < zlo + ZT2; z++) {
        const int zp = z + 1 > ZDIM - 1 ? ZDIM - 1 : z + 1;
        uint32_t nw[3];
        nw[0] = tb[zp * WPLANE + r0];
        nw[1] = tb[zp * WPLANE + r1];
        nw[2] = tb[zp * WPLANE + r2];

        // A[y'] = b[z-1] + 2*b[z] + b[z+1]  (3 bit-planes, value <= 4)
        uint32_t A0[3], A1[3], A2[3];
        #pragma unroll
        for (int i = 0; i < 3; i++) {
            uint32_t c = o2[i] & nw[i];
            A0[i] = o2[i] ^ nw[i];
            A1[i] = c ^ o1[i];
            A2[i] = c & o1[i];
        }

        // U = A[ym] + A[yp]  (4 bit-planes, value <= 8)
        uint32_t U0, U1, U2, U3;
        {
            uint32_t c0 = A0[0] & A0[2];
            U0 = A0[0] ^ A0[2];
            uint32_t t1 = A1[0] ^ A1[2], g1 = A1[0] & A1[2];
            U1 = t1 ^ c0;
            uint32_t c1 = g1 | (t1 & c0);
            uint32_t t2 = A2[0] ^ A2[2], g2 = A2[0] & A2[2];
            U2 = t2 ^ c1;
            U3 = g2 | (t2 & c1);
        }

        // S = U + 2*A[y]  (5 bit-planes, value <= 16)
        uint32_t S0, S1, S2, S3, S4;
        {
            S0 = U0;
            uint32_t ca = U1 & A0[1];
            S1 = U1 ^ A0[1];
            uint32_t b = U2 ^ A1[1], cb = U2 & A1[1];
            S2 = b ^ ca;
            uint32_t c2 = cb | (b & ca);
            uint32_t d = U3 ^ A2[1], cd = U3 & A2[1];
            S3 = d ^ c2;
            S4 = cd | (d & c2);
        }

        // boundary S values (5-bit) at bit0 / bit31
        uint32_t bot = (S0 & 1u) | ((S1 & 1u) << 1) | ((S2 & 1u) << 2)
                     | ((S3 & 1u) << 3) | ((S4 & 1u) << 4);
        uint32_t top = (S0 >> 31) | ((S1 >> 31) << 1) | ((S2 >> 31) << 2)
                     | ((S3 >> 31) << 3) | ((S4 >> 31) << 4);

        uint32_t Lnb = __shfl_up_sync(0xFFFFFFFFu, top, 1);
        uint32_t Rnb = __shfl_down_sync(0xFFFFFFFFu, bot, 1);
        uint32_t L = (xw == 0)      ? bot : Lnb;   // reflect: S[-1] = S[0]
        uint32_t R = (xw == XW - 1) ? top : Rnb;   // reflect: S[W]  = S[W-1]

        // shifted planes: SL = S at x-1, SR = S at x+1
        uint32_t SL0 = (S0 << 1) | (L & 1u);
        uint32_t SL1 = (S1 << 1) | ((L >> 1) & 1u);
        uint32_t SL2 = (S2 << 1) | ((L >> 2) & 1u);
        uint32_t SL3 = (S3 << 1) | ((L >> 3) & 1u);
        uint32_t SL4 = (S4 << 1) | ((L >> 4) & 1u);
        uint32_t SR0 = (S0 >> 1) | ((R & 1u) << 31);
        uint32_t SR1 = (S1 >> 1) | (((R >> 1) & 1u) << 31);
        uint32_t SR2 = (S2 >> 1) | (((R >> 2) & 1u) << 31);
        uint32_t SR3 = (S3 >> 1) | (((R >> 3) & 1u) << 31);
        uint32_t SR4 = (S4 >> 1) | (((R >> 4) & 1u) << 31);

        // gt = (SR > SL), 5-bit bit-sliced comparator (LSB -> MSB)
        uint32_t gt = SR0 & ~SL0;
        gt = (SR1 & ~SL1) | (~(SR1 ^ SL1) & gt);
        gt = (SR2 & ~SL2) | (~(SR2 ^ SL2) & gt);
        gt = (SR3 & ~SL3) | (~(SR3 ^ SL3) & gt);
        gt = (SR4 & ~SL4) | (~(SR4 ^ SL4) & gt);

        if (active) cnt += __popc(gt);

        o2[0] = o1[0]; o2[1] = o1[1]; o2[2] = o1[2];
        o1[0] = nw[0]; o1[1] = nw[1]; o1[2] = nw[2];
    }

    // deterministic block reduction of cnt_edge
    __shared__ float red[BTHR2 / 32];
    __shared__ unsigned s_ticket;
    float fe = (float)cnt;
    #pragma unroll
    for (int o = 16; o; o >>= 1)
        fe += __shfl_xor_sync(0xFFFFFFFFu, fe, o);
    int warp = threadIdx.x >> 5, lane = threadIdx.x & 31;
    if (lane == 0) red[warp] = fe;
    __syncthreads();
    if (warp == 0) {
        float v = lane < (BTHR2 / 32) ? red[lane] : 0.f;
        #pragma unroll
        for (int o = 8; o; o >>= 1)
            v += __shfl_xor_sync(0xFFFFFFFFu, v, o);
        if (lane == 0)
            g_partB[bc * NTB + blockIdx.y * NYC2 + blockIdx.x] = v;
    }

    // ---- last-block finalize ----
    __threadfence();
    if (threadIdx.x == 0)
        s_ticket = atomicAdd(&g_done, 1u);
    __syncthreads();
    if (s_ticket != NBLK_B - 1) return;

    // This is the last block: all g_partA (prior kernel) and g_partB
    // (fenced before the counter) writes are visible.
    if (threadIdx.x == 0) g_done = 0;              // reset for next replay

    __shared__ float s[NBC][5];
    {
        // warp w handles bc w (12 warps)
        float a0 = 0.f, a1 = 0.f, a2 = 0.f, a3 = 0.f, a4 = 0.f;
        for (int i = lane; i < ABLK; i += 32) {
            const float* p = &g_partA[(warp * ABLK + i) * 4];
            a0 += p[0]; a1 += p[1]; a2 += p[2]; a3 += p[3];
        }
        if (lane < NTB) a4 = g_partB[warp * NTB + lane];
        #pragma unroll
        for (int o = 16; o; o >>= 1) {
            a0 += __shfl_xor_sync(0xFFFFFFFFu, a0, o);
            a1 += __shfl_xor_sync(0xFFFFFFFFu, a1, o);
            a2 += __shfl_xor_sync(0xFFFFFFFFu, a2, o);
            a3 += __shfl_xor_sync(0xFFFFFFFFu, a3, o);
            a4 += __shfl_xor_sync(0xFFFFFFFFu, a4, o);
        }
        if (lane == 0) {
            s[warp][0] = a0; s[warp][1] = a1; s[warp][2] = a2;
            s[warp][3] = a3; s[warp][4] = a4;
        }
    }
    __syncthreads();

    if (threadIdx.x == 0) {
        const float vox = (float)VOXBC;
        float loss = 0.f;
        for (int b = 0; b < BDIM; b++) {
            float f[CDIM];
            for (int c = 0; c < CDIM; c++) f[c] = s[b * CDIM + c][0] / vox;
            float med = med3f(f[0], f[1], f[2]);
            float mn  = fminf(fminf(f[0], f[1]), f[2]);
            float w0  = 2.0f * med / (mn + 1e-5f);
            float nom = 0.f, den = 0.f;
            for (int c = 0; c < CDIM; c++) {
                const float* p = s[b * CDIM + c];
                float cw  = med / (f[c] + 1e-5f) * p[3] + w0 * p[4];
                nom += cw * p[2];                       // sum(p*m)
                den += cw * (p[1] + p[0]) + 1e-7f;      // sum(p)+sum(m)
            }
            loss += 1.0f - 2.0f * nom / den;
        }
        out[0] = loss / (float)BDIM;
    }
}

extern "C" void kernel_launch(void* const* d_in, const int* in_sizes, int n_in,
                              void* d_out, int out_size)
{
    const float* output = (const float*)d_in[0];
    const float* masks  = (const float*)d_in[1];
    const float* thr    = (const float*)d_in[2];

    dim3 ga(ABLK, NBC);          // 288 x 12
    kA<<<ga, ATHR>>>(output, masks, thr);

    dim3 gb(NYC2, NZC2, NBC);    // 4 x 4 x 12 = 192 blocks
    kB<<<gb, BTHR2>>>((float*)d_out);
}

// round 8
// speedup vs baseline: 1.0901x; 1.0901x over previous
#include <cuda_runtime.h>
#include <cstdint>

// Fixed shapes: B=4, C=3, Z=64, H=192, W=192
#define BDIM 4
#define CDIM 3
#define ZDIM 64
#define HDIM 192
#define WDIM 192
#define HW    (HDIM * WDIM)          // 36864
#define NBC   (BDIM * CDIM)          // 12
#define VOXBC (ZDIM * HW)            // 2359296 voxels per (b,c)
#define XW    (WDIM / 32)            // 6 packed words per x-row
#define WPLANE (HDIM * XW)           // 1152 words per z-plane
#define WBC   (VOXBC / 32)           // 73728 words per (b,c)

// Kernel A config
#define ABLK 288                     // blocks per (b,c)
#define ATHR 256
#define AVOX (VOXBC / ABLK)          // 8192 voxels per block
#define AF4  (AVOX / 4 / ATHR)       // 8 float4 per thread

// Kernel B config (stencil + fused finalize)
#define YT2  32
#define NYC2 (HDIM / YT2)            // 6
#define ZT2  8
#define NZC2 (ZDIM / ZT2)            // 8
#define BTHR2 256                    // 32 rows x 8 lanes; 8 warps
#define NWARP_B (BTHR2 / 32)         // 8
#define NTB  (NYC2 * NZC2)           // 48 tiles per bc
#define NBLK_B (NYC2 * NZC2 * NBC)   // 576 blocks total

__device__ uint32_t g_tsw[NBC * WBC];            // 3.5 MB bit-packed ts
__device__ float    g_partA[NBC * ABLK * 4];     // {sum_m, sum_p, sum_pm, cnt_eq}
__device__ float    g_partB[NBC * NTB];          // cnt_edge per tile
__device__ unsigned g_done = 0;                  // last-block ticket (self-resetting)

// ---------------------------------------------------------------------------
// Kernel A: stream output+masks once; reduce 4 scalars; emit bit-packed ts.
// ---------------------------------------------------------------------------
__global__ __launch_bounds__(ATHR)
void kA(const float* __restrict__ output,
        const float* __restrict__ masks,
        const float* __restrict__ thr_ptr)
{
    const int bc = blockIdx.y;
    const float thr = *thr_ptr;
    const size_t base = (size_t)bc * VOXBC + (size_t)blockIdx.x * AVOX;

    const float4* op = reinterpret_cast<const float4*>(output) + base / 4;
    const float4* mp = reinterpret_cast<const float4*>(masks)  + base / 4;
    uint32_t*     tw = g_tsw + base / 32;

    const int lane8 = threadIdx.x & 7;
    const int sh = lane8 * 4;

    float sum_p = 0.f, sum_m = 0.f, sum_pm = 0.f, cnt_eq = 0.f;

    #pragma unroll
    for (int j = 0; j < AF4; j++) {
        int idx = j * ATHR + threadIdx.x;          // coalesced float4
        float4 v = op[idx];
        float4 m = mp[idx];

        uint32_t b0 = v.x > thr;
        uint32_t b1 = v.y > thr;
        uint32_t b2 = v.z > thr;
        uint32_t b3 = v.w > thr;

        // pack 8 lanes' nibbles into one word (32 voxels)
        uint32_t w = (b0 | (b1 << 1) | (b2 << 2) | (b3 << 3)) << sh;
        w |= __shfl_xor_sync(0xFFFFFFFFu, w, 1);
        w |= __shfl_xor_sync(0xFFFFFFFFu, w, 2);
        w |= __shfl_xor_sync(0xFFFFFFFFu, w, 4);
        if (lane8 == 0) tw[idx >> 3] = w;

        sum_p  += (v.x + v.y) + (v.z + v.w);
        sum_m  += (m.x + m.y) + (m.z + m.w);
        sum_pm += v.x * m.x + v.y * m.y + v.z * m.z + v.w * m.w;

        float t0 = b0 ? 1.0f : 0.0f;
        float t1 = b1 ? 1.0f : 0.0f;
        float t2 = b2 ? 1.0f : 0.0f;
        float t3 = b3 ? 1.0f : 0.0f;
        cnt_eq += (float)((t0 == m.x) + (t1 == m.y) + (t2 == m.z) + (t3 == m.w));
    }

    __shared__ float red[ATHR / 32][4];
    #pragma unroll
    for (int o = 16; o; o >>= 1) {
        sum_m  += __shfl_xor_sync(0xFFFFFFFFu, sum_m,  o);
        sum_p  += __shfl_xor_sync(0xFFFFFFFFu, sum_p,  o);
        sum_pm += __shfl_xor_sync(0xFFFFFFFFu, sum_pm, o);
        cnt_eq += __shfl_xor_sync(0xFFFFFFFFu, cnt_eq, o);
    }
    int warp = threadIdx.x >> 5, lane = threadIdx.x & 31;
    if (lane == 0) {
        red[warp][0] = sum_m; red[warp][1] = sum_p;
        red[warp][2] = sum_pm; red[warp][3] = cnt_eq;
    }
    __syncthreads();
    if (warp == 0) {
        float v0 = lane < 8 ? red[lane][0] : 0.f;
        float v1 = lane < 8 ? red[lane][1] : 0.f;
        float v2 = lane < 8 ? red[lane][2] : 0.f;
        float v3 = lane < 8 ? red[lane][3] : 0.f;
        #pragma unroll
        for (int o = 4; o; o >>= 1) {
            v0 += __shfl_xor_sync(0xFFFFFFFFu, v0, o);
            v1 += __shfl_xor_sync(0xFFFFFFFFu, v1, o);
            v2 += __shfl_xor_sync(0xFFFFFFFFu, v2, o);
            v3 += __shfl_xor_sync(0xFFFFFFFFu, v3, o);
        }
        if (lane == 0) {
            float* dst = &g_partA[(bc * ABLK + blockIdx.x) * 4];
            dst[0] = v0; dst[1] = v1; dst[2] = v2; dst[3] = v3;
        }
    }
}

__device__ __forceinline__ float med3f(float a, float b, float c) {
    return fmaxf(fminf(a, b), fminf(fmaxf(a, b), c));
}

// ---------------------------------------------------------------------------
// Kernel B: bit-sliced Sobel edge count + last-block finalize.
// Each thread owns one (y, x-word); x-neighbor bits via shuffles.
// ---------------------------------------------------------------------------
__global__ __launch_bounds__(BTHR2)
void kB(float* __restrict__ out)
{
    const int bc  = blockIdx.z;
    const int y   = blockIdx.x * YT2 + (threadIdx.x >> 3);
    const int xw  = threadIdx.x & 7;
    const bool active = xw < XW;
    const int xwc = active ? xw : XW - 1;
    const int zlo = blockIdx.y * ZT2;

    const uint32_t* tb = g_tsw + (size_t)bc * WBC;
    const int ym = y - 1 < 0 ? 0 : y - 1;
    const int yp = y + 1 > HDIM - 1 ? HDIM - 1 : y + 1;
    const int r0 = ym * XW + xwc, r1 = y * XW + xwc, r2 = yp * XW + xwc;

    // rolling z-window of packed bits for 3 y-rows
    uint32_t o2[3], o1[3];
    {
        int zm0 = zlo - 1 < 0 ? 0 : zlo - 1;
        o2[0] = tb[zm0 * WPLANE + r0];
        o2[1] = tb[zm0 * WPLANE + r1];
        o2[2] = tb[zm0 * WPLANE + r2];
        o1[0] = tb[zlo * WPLANE + r0];
        o1[1] = tb[zlo * WPLANE + r1];
        o1[2] = tb[zlo * WPLANE + r2];
    }

    int cnt = 0;
    #pragma unroll
    for (int z = zlo; z < zlo + ZT2; z++) {
        const int zp = z + 1 > ZDIM - 1 ? ZDIM - 1 : z + 1;
        uint32_t nw[3];
        nw[0] = tb[zp * WPLANE + r0];
        nw[1] = tb[zp * WPLANE + r1];
        nw[2] = tb[zp * WPLANE + r2];

        // A[y'] = b[z-1] + 2*b[z] + b[z+1]  (3 bit-planes, value <= 4)
        uint32_t A0[3], A1[3], A2[3];
        #pragma unroll
        for (int i = 0; i < 3; i++) {
            uint32_t c = o2[i] & nw[i];
            A0[i] = o2[i] ^ nw[i];
            A1[i] = c ^ o1[i];
            A2[i] = c & o1[i];
        }

        // U = A[ym] + A[yp]  (4 bit-planes, value <= 8)
        uint32_t U0, U1, U2, U3;
        {
            uint32_t c0 = A0[0] & A0[2];
            U0 = A0[0] ^ A0[2];
            uint32_t t1 = A1[0] ^ A1[2], g1 = A1[0] & A1[2];
            U1 = t1 ^ c0;
            uint32_t c1 = g1 | (t1 & c0);
            uint32_t t2 = A2[0] ^ A2[2], g2 = A2[0] & A2[2];
            U2 = t2 ^ c1;
            U3 = g2 | (t2 & c1);
        }

        // S = U + 2*A[y]  (5 bit-planes, value <= 16)
        uint32_t S0, S1, S2, S3, S4;
        {
            S0 = U0;
            uint32_t ca = U1 & A0[1];
            S1 = U1 ^ A0[1];
            uint32_t b = U2 ^ A1[1], cb = U2 & A1[1];
            S2 = b ^ ca;
            uint32_t c2 = cb | (b & ca);
            uint32_t d = U3 ^ A2[1], cd = U3 & A2[1];
            S3 = d ^ c2;
            S4 = cd | (d & c2);
        }

        // boundary S values (5-bit) at bit0 / bit31
        uint32_t bot = (S0 & 1u) | ((S1 & 1u) << 1) | ((S2 & 1u) << 2)
                     | ((S3 & 1u) << 3) | ((S4 & 1u) << 4);
        uint32_t top = (S0 >> 31) | ((S1 >> 31) << 1) | ((S2 >> 31) << 2)
                     | ((S3 >> 31) << 3) | ((S4 >> 31) << 4);

        uint32_t Lnb = __shfl_up_sync(0xFFFFFFFFu, top, 1);
        uint32_t Rnb = __shfl_down_sync(0xFFFFFFFFu, bot, 1);
        uint32_t L = (xw == 0)      ? bot : Lnb;   // reflect: S[-1] = S[0]
        uint32_t R = (xw == XW - 1) ? top : Rnb;   // reflect: S[W]  = S[W-1]

        // shifted planes: SL = S at x-1, SR = S at x+1
        uint32_t SL0 = (S0 << 1) | (L & 1u);
        uint32_t SL1 = (S1 << 1) | ((L >> 1) & 1u);
        uint32_t SL2 = (S2 << 1) | ((L >> 2) & 1u);
        uint32_t SL3 = (S3 << 1) | ((L >> 3) & 1u);
        uint32_t SL4 = (S4 << 1) | ((L >> 4) & 1u);
        uint32_t SR0 = (S0 >> 1) | ((R & 1u) << 31);
        uint32_t SR1 = (S1 >> 1) | (((R >> 1) & 1u) << 31);
        uint32_t SR2 = (S2 >> 1) | (((R >> 2) & 1u) << 31);
        uint32_t SR3 = (S3 >> 1) | (((R >> 3) & 1u) << 31);
        uint32_t SR4 = (S4 >> 1) | (((R >> 4) & 1u) << 31);

        // gt = (SR > SL), 5-bit bit-sliced comparator (LSB -> MSB)
        uint32_t gt = SR0 & ~SL0;
        gt = (SR1 & ~SL1) | (~(SR1 ^ SL1) & gt);
        gt = (SR2 & ~SL2) | (~(SR2 ^ SL2) & gt);
        gt = (SR3 & ~SL3) | (~(SR3 ^ SL3) & gt);
        gt = (SR4 & ~SL4) | (~(SR4 ^ SL4) & gt);

        if (active) cnt += __popc(gt);

        o2[0] = o1[0]; o2[1] = o1[1]; o2[2] = o1[2];
        o1[0] = nw[0]; o1[1] = nw[1]; o1[2] = nw[2];
    }

    // deterministic block reduction of cnt_edge
    __shared__ float red[NWARP_B];
    __shared__ unsigned s_ticket;
    float fe = (float)cnt;
    #pragma unroll
    for (int o = 16; o; o >>= 1)
        fe += __shfl_xor_sync(0xFFFFFFFFu, fe, o);
    int warp = threadIdx.x >> 5, lane = threadIdx.x & 31;
    if (lane == 0) red[warp] = fe;
    __syncthreads();
    if (warp == 0) {
        float v = lane < NWARP_B ? red[lane] : 0.f;
        #pragma unroll
        for (int o = 4; o; o >>= 1)
            v += __shfl_xor_sync(0xFFFFFFFFu, v, o);
        if (lane == 0)
            g_partB[bc * NTB + blockIdx.y * NYC2 + blockIdx.x] = v;
    }

    // ---- last-block finalize ----
    __threadfence();
    if (threadIdx.x == 0)
        s_ticket = atomicAdd(&g_done, 1u);
    __syncthreads();
    if (s_ticket != NBLK_B - 1) return;

    if (threadIdx.x == 0) g_done = 0;              // reset for next replay

    __shared__ float s[NBC][5];
    // warp w handles bc w and w+8 (lane-strided, float4 loads -> high MLP)
    for (int bcf = warp; bcf < NBC; bcf += NWARP_B) {
        float a0 = 0.f, a1 = 0.f, a2 = 0.f, a3 = 0.f, a4 = 0.f;
        const float4* pa = reinterpret_cast<const float4*>(&g_partA[bcf * ABLK * 4]);
        for (int i = lane; i < ABLK; i += 32) {
            float4 p = pa[i];
            a0 += p.x; a1 += p.y; a2 += p.z; a3 += p.w;
        }
        for (int i = lane; i < NTB; i += 32)
            a4 += g_partB[bcf * NTB + i];
        #pragma unroll
        for (int o = 16; o; o >>= 1) {
            a0 += __shfl_xor_sync(0xFFFFFFFFu, a0, o);
            a1 += __shfl_xor_sync(0xFFFFFFFFu, a1, o);
            a2 += __shfl_xor_sync(0xFFFFFFFFu, a2, o);
            a3 += __shfl_xor_sync(0xFFFFFFFFu, a3, o);
            a4 += __shfl_xor_sync(0xFFFFFFFFu, a4, o);
        }
        if (lane == 0) {
            s[bcf][0] = a0; s[bcf][1] = a1; s[bcf][2] = a2;
            s[bcf][3] = a3; s[bcf][4] = a4;
        }
    }
    __syncthreads();

    if (threadIdx.x == 0) {
        const float vox = (float)VOXBC;
        float loss = 0.f;
        for (int b = 0; b < BDIM; b++) {
            float f[CDIM];
            for (int c = 0; c < CDIM; c++) f[c] = s[b * CDIM + c][0] / vox;
            float med = med3f(f[0], f[1], f[2]);
            float mn  = fminf(fminf(f[0], f[1]), f[2]);
            float w0  = 2.0f * med / (mn + 1e-5f);
            float nom = 0.f, den = 0.f;
            for (int c = 0; c < CDIM; c++) {
                const float* p = s[b * CDIM + c];
                float cw  = med / (f[c] + 1e-5f) * p[3] + w0 * p[4];
                nom += cw * p[2];                       // sum(p*m)
                den += cw * (p[1] + p[0]) + 1e-7f;      // sum(p)+sum(m)
            }
            loss += 1.0f - 2.0f * nom / den;
        }
        out[0] = loss / (float)BDIM;
    }
}

extern "C" void kernel_launch(void* const* d_in, const int* in_sizes, int n_in,
                              void* d_out, int out_size)
{
    const float* output = (const float*)d_in[0];
    const float* masks  = (const float*)d_in[1];
    const float* thr    = (const float*)d_in[2];

    dim3 ga(ABLK, NBC);          // 288 x 12
    kA<<<ga, ATHR>>>(output, masks, thr);

    dim3 gb(NYC2, NZC2, NBC);    // 6 x 8 x 12 = 576 blocks
    kB<<<gb, BTHR2>>>((float*)d_out);
}

// round 9
// speedup vs baseline: 1.1338x; 1.0400x over previous
#include <cuda_runtime.h>
#include <cstdint>

// Fixed shapes: B=4, C=3, Z=64, H=192, W=192
#define BDIM 4
#define CDIM 3
#define ZDIM 64
#define HDIM 192
#define WDIM 192
#define HW    (HDIM * WDIM)          // 36864
#define NBC   (BDIM * CDIM)          // 12
#define VOXBC (ZDIM * HW)            // 2359296 voxels per (b,c)
#define XW    (WDIM / 32)            // 6 packed words per x-row
#define WPLANE (HDIM * XW)           // 1152 words per z-plane
#define WBC   (VOXBC / 32)           // 73728 words per (b,c)

// Kernel A config
#define ABLK 288                     // blocks per (b,c)
#define ATHR 256
#define AVOX (VOXBC / ABLK)          // 8192 voxels per block
#define AF4  (AVOX / 4 / ATHR)       // 8 float4 per thread

// Kernel B config (stencil + fused finalize)
#define YT2  32
#define NYC2 (HDIM / YT2)            // 6
#define ZT2  8
#define NZC2 (ZDIM / ZT2)            // 8
#define BTHR2 256                    // 32 rows x 8 lanes; 8 warps
#define NWARP_B (BTHR2 / 32)         // 8
#define NTB  (NYC2 * NZC2)           // 48 tiles per bc
#define NBLK_B (NYC2 * NZC2 * NBC)   // 576 blocks total

__device__ uint32_t g_tsw[NBC * WBC];            // 3.5 MB bit-packed ts
__device__ float    g_partA[NBC * ABLK * 4];     // {sum_m, sum_p, sum_pm, cnt_eq}
__device__ float    g_partB[NBC * NTB];          // cnt_edge per tile
__device__ unsigned g_done = 0;                  // last-block ticket (self-resetting)

// ---------------------------------------------------------------------------
// Kernel A: stream output+masks once; reduce 4 scalars; emit bit-packed ts.
// ---------------------------------------------------------------------------
__global__ __launch_bounds__(ATHR)
void kA(const float* __restrict__ output,
        const float* __restrict__ masks,
        const float* __restrict__ thr_ptr)
{
    const int bc = blockIdx.y;
    const float thr = *thr_ptr;
    const size_t base = (size_t)bc * VOXBC + (size_t)blockIdx.x * AVOX;

    const float4* op = reinterpret_cast<const float4*>(output) + base / 4;
    const float4* mp = reinterpret_cast<const float4*>(masks)  + base / 4;
    uint32_t*     tw = g_tsw + base / 32;

    const int lane8 = threadIdx.x & 7;
    const int sh = lane8 * 4;

    float sum_p = 0.f, sum_m = 0.f, sum_pm = 0.f, cnt_eq = 0.f;

    #pragma unroll
    for (int j = 0; j < AF4; j++) {
        int idx = j * ATHR + threadIdx.x;          // coalesced float4
        float4 v = op[idx];
        float4 m = mp[idx];

        uint32_t b0 = v.x > thr;
        uint32_t b1 = v.y > thr;
        uint32_t b2 = v.z > thr;
        uint32_t b3 = v.w > thr;

        // pack 8 lanes' nibbles into one word (32 voxels)
        uint32_t w = (b0 | (b1 << 1) | (b2 << 2) | (b3 << 3)) << sh;
        w |= __shfl_xor_sync(0xFFFFFFFFu, w, 1);
        w |= __shfl_xor_sync(0xFFFFFFFFu, w, 2);
        w |= __shfl_xor_sync(0xFFFFFFFFu, w, 4);
        if (lane8 == 0) tw[idx >> 3] = w;

        sum_p  += (v.x + v.y) + (v.z + v.w);
        sum_m  += (m.x + m.y) + (m.z + m.w);
        sum_pm += v.x * m.x + v.y * m.y + v.z * m.z + v.w * m.w;

        float t0 = b0 ? 1.0f : 0.0f;
        float t1 = b1 ? 1.0f : 0.0f;
        float t2 = b2 ? 1.0f : 0.0f;
        float t3 = b3 ? 1.0f : 0.0f;
        cnt_eq += (float)((t0 == m.x) + (t1 == m.y) + (t2 == m.z) + (t3 == m.w));
    }

    __shared__ float red[ATHR / 32][4];
    #pragma unroll
    for (int o = 16; o; o >>= 1) {
        sum_m  += __shfl_xor_sync(0xFFFFFFFFu, sum_m,  o);
        sum_p  += __shfl_xor_sync(0xFFFFFFFFu, sum_p,  o);
        sum_pm += __shfl_xor_sync(0xFFFFFFFFu, sum_pm, o);
        cnt_eq += __shfl_xor_sync(0xFFFFFFFFu, cnt_eq, o);
    }
    int warp = threadIdx.x >> 5, lane = threadIdx.x & 31;
    if (lane == 0) {
        red[warp][0] = sum_m; red[warp][1] = sum_p;
        red[warp][2] = sum_pm; red[warp][3] = cnt_eq;
    }
    __syncthreads();
    if (warp == 0) {
        float v0 = lane < 8 ? red[lane][0] : 0.f;
        float v1 = lane < 8 ? red[lane][1] : 0.f;
        float v2 = lane < 8 ? red[lane][2] : 0.f;
        float v3 = lane < 8 ? red[lane][3] : 0.f;
        #pragma unroll
        for (int o = 4; o; o >>= 1) {
            v0 += __shfl_xor_sync(0xFFFFFFFFu, v0, o);
            v1 += __shfl_xor_sync(0xFFFFFFFFu, v1, o);
            v2 += __shfl_xor_sync(0xFFFFFFFFu, v2, o);
            v3 += __shfl_xor_sync(0xFFFFFFFFu, v3, o);
        }
        if (lane == 0) {
            float* dst = &g_partA[(bc * ABLK + blockIdx.x) * 4];
            dst[0] = v0; dst[1] = v1; dst[2] = v2; dst[3] = v3;
        }
    }
}

__device__ __forceinline__ float med3f(float a, float b, float c) {
    return fmaxf(fminf(a, b), fminf(fmaxf(a, b), c));
}

// ---------------------------------------------------------------------------
// Kernel B: bit-sliced Sobel edge count + last-block finalize.
// All 30 plane-row words are prefetched into registers BEFORE the compute
// loop (addresses are loop-invariant) -> MLP ~30 instead of 3.
// ---------------------------------------------------------------------------
__global__ __launch_bounds__(BTHR2, 4)
void kB(float* __restrict__ out)
{
    const int bc  = blockIdx.z;
    const int y   = blockIdx.x * YT2 + (threadIdx.x >> 3);
    const int xw  = threadIdx.x & 7;
    const bool active = xw < XW;
    const int xwc = active ? xw : XW - 1;
    const int zlo = blockIdx.y * ZT2;

    const uint32_t* tb = g_tsw + (size_t)bc * WBC;
    const int ym = y - 1 < 0 ? 0 : y - 1;
    const int yp = y + 1 > HDIM - 1 ? HDIM - 1 : y + 1;
    const int r0 = ym * XW + xwc, r1 = y * XW + xwc, r2 = yp * XW + xwc;

    // Prefetch ALL planes [zlo-1 .. zlo+ZT2] (clamped) x 3 rows -> registers.
    uint32_t P0[ZT2 + 2], P1[ZT2 + 2], P2[ZT2 + 2];
    #pragma unroll
    for (int k = 0; k < ZT2 + 2; k++) {
        int zp = zlo - 1 + k;
        zp = zp < 0 ? 0 : (zp > ZDIM - 1 ? ZDIM - 1 : zp);   // reflect z
        const uint32_t* pl = tb + zp * WPLANE;
        P0[k] = pl[r0];
        P1[k] = pl[r1];
        P2[k] = pl[r2];
    }

    int cnt = 0;
    #pragma unroll
    for (int i = 0; i < ZT2; i++) {
        const uint32_t o2[3] = {P0[i],     P1[i],     P2[i]};
        const uint32_t o1[3] = {P0[i + 1], P1[i + 1], P2[i + 1]};
        const uint32_t nw[3] = {P0[i + 2], P1[i + 2], P2[i + 2]};

        // A[y'] = b[z-1] + 2*b[z] + b[z+1]  (3 bit-planes, value <= 4)
        uint32_t A0[3], A1[3], A2[3];
        #pragma unroll
        for (int q = 0; q < 3; q++) {
            uint32_t c = o2[q] & nw[q];
            A0[q] = o2[q] ^ nw[q];
            A1[q] = c ^ o1[q];
            A2[q] = c & o1[q];
        }

        // U = A[ym] + A[yp]  (4 bit-planes, value <= 8)
        uint32_t U0, U1, U2, U3;
        {
            uint32_t c0 = A0[0] & A0[2];
            U0 = A0[0] ^ A0[2];
            uint32_t t1 = A1[0] ^ A1[2], g1 = A1[0] & A1[2];
            U1 = t1 ^ c0;
            uint32_t c1 = g1 | (t1 & c0);
            uint32_t t2 = A2[0] ^ A2[2], g2 = A2[0] & A2[2];
            U2 = t2 ^ c1;
            U3 = g2 | (t2 & c1);
        }

        // S = U + 2*A[y]  (5 bit-planes, value <= 16)
        uint32_t S0, S1, S2, S3, S4;
        {
            S0 = U0;
            uint32_t ca = U1 & A0[1];
            S1 = U1 ^ A0[1];
            uint32_t b = U2 ^ A1[1], cb = U2 & A1[1];
            S2 = b ^ ca;
            uint32_t c2 = cb | (b & ca);
            uint32_t d = U3 ^ A2[1], cd = U3 & A2[1];
            S3 = d ^ c2;
            S4 = cd | (d & c2);
        }

        // boundary S values (5-bit) at bit0 / bit31
        uint32_t bot = (S0 & 1u) | ((S1 & 1u) << 1) | ((S2 & 1u) << 2)
                     | ((S3 & 1u) << 3) | ((S4 & 1u) << 4);
        uint32_t top = (S0 >> 31) | ((S1 >> 31) << 1) | ((S2 >> 31) << 2)
                     | ((S3 >> 31) << 3) | ((S4 >> 31) << 4);

        uint32_t Lnb = __shfl_up_sync(0xFFFFFFFFu, top, 1);
        uint32_t Rnb = __shfl_down_sync(0xFFFFFFFFu, bot, 1);
        uint32_t L = (xw == 0)      ? bot : Lnb;   // reflect: S[-1] = S[0]
        uint32_t R = (xw == XW - 1) ? top : Rnb;   // reflect: S[W]  = S[W-1]

        // shifted planes: SL = S at x-1, SR = S at x+1
        uint32_t SL0 = (S0 << 1) | (L & 1u);
        uint32_t SL1 = (S1 << 1) | ((L >> 1) & 1u);
        uint32_t SL2 = (S2 << 1) | ((L >> 2) & 1u);
        uint32_t SL3 = (S3 << 1) | ((L >> 3) & 1u);
        uint32_t SL4 = (S4 << 1) | ((L >> 4) & 1u);
        uint32_t SR0 = (S0 >> 1) | ((R & 1u) << 31);
        uint32_t SR1 = (S1 >> 1) | (((R >> 1) & 1u) << 31);
        uint32_t SR2 = (S2 >> 1) | (((R >> 2) & 1u) << 31);
        uint32_t SR3 = (S3 >> 1) | (((R >> 3) & 1u) << 31);
        uint32_t SR4 = (S4 >> 1) | (((R >> 4) & 1u) << 31);

        // gt = (SR > SL), 5-bit bit-sliced comparator (LSB -> MSB)
        uint32_t gt = SR0 & ~SL0;
        gt = (SR1 & ~SL1) | (~(SR1 ^ SL1) & gt);
        gt = (SR2 & ~SL2) | (~(SR2 ^ SL2) & gt);
        gt = (SR3 & ~SL3) | (~(SR3 ^ SL3) & gt);
        gt = (SR4 & ~SL4) | (~(SR4 ^ SL4) & gt);

        if (active) cnt += __popc(gt);
    }

    // deterministic block reduction of cnt_edge
    __shared__ float red[NWARP_B];
    __shared__ unsigned s_ticket;
    float fe = (float)cnt;
    #pragma unroll
    for (int o = 16; o; o >>= 1)
        fe += __shfl_xor_sync(0xFFFFFFFFu, fe, o);
    int warp = threadIdx.x >> 5, lane = threadIdx.x & 31;
    if (lane == 0) red[warp] = fe;
    __syncthreads();
    if (warp == 0) {
        float v = lane < NWARP_B ? red[lane] : 0.f;
        #pragma unroll
        for (int o = 4; o; o >>= 1)
            v += __shfl_xor_sync(0xFFFFFFFFu, v, o);
        if (lane == 0)
            g_partB[bc * NTB + blockIdx.y * NYC2 + blockIdx.x] = v;
    }

    // ---- last-block finalize ----
    __threadfence();
    if (threadIdx.x == 0)
        s_ticket = atomicAdd(&g_done, 1u);
    __syncthreads();
    if (s_ticket != NBLK_B - 1) return;

    if (threadIdx.x == 0) g_done = 0;              // reset for next replay

    __shared__ float s[NBC][5];
    // warp w handles bc w and w+8 (lane-strided, float4 loads -> high MLP)
    for (int bcf = warp; bcf < NBC; bcf += NWARP_B) {
        float a0 = 0.f, a1 = 0.f, a2 = 0.f, a3 = 0.f, a4 = 0.f;
        const float4* pa = reinterpret_cast<const float4*>(&g_partA[bcf * ABLK * 4]);
        for (int i = lane; i < ABLK; i += 32) {
            float4 p = pa[i];
            a0 += p.x; a1 += p.y; a2 += p.z; a3 += p.w;
        }
        for (int i = lane; i < NTB; i += 32)
            a4 += g_partB[bcf * NTB + i];
        #pragma unroll
        for (int o = 16; o; o >>= 1) {
            a0 += __shfl_xor_sync(0xFFFFFFFFu, a0, o);
            a1 += __shfl_xor_sync(0xFFFFFFFFu, a1, o);
            a2 += __shfl_xor_sync(0xFFFFFFFFu, a2, o);
            a3 += __shfl_xor_sync(0xFFFFFFFFu, a3, o);
            a4 += __shfl_xor_sync(0xFFFFFFFFu, a4, o);
        }
        if (lane == 0) {
            s[bcf][0] = a0; s[bcf][1] = a1; s[bcf][2] = a2;
            s[bcf][3] = a3; s[bcf][4] = a4;
        }
    }
    __syncthreads();

    if (threadIdx.x == 0) {
        const float vox = (float)VOXBC;
        float loss = 0.f;
        for (int b = 0; b < BDIM; b++) {
            float f[CDIM];
            for (int c = 0; c < CDIM; c++) f[c] = s[b * CDIM + c][0] / vox;
            float med = med3f(f[0], f[1], f[2]);
            float mn  = fminf(fminf(f[0], f[1]), f[2]);
            float w0  = 2.0f * med / (mn + 1e-5f);
            float nom = 0.f, den = 0.f;
            for (int c = 0; c < CDIM; c++) {
                const float* p = s[b * CDIM + c];
                float cw  = med / (f[c] + 1e-5f) * p[3] + w0 * p[4];
                nom += cw * p[2];                       // sum(p*m)
                den += cw * (p[1] + p[0]) + 1e-7f;      // sum(p)+sum(m)
            }
            loss += 1.0f - 2.0f * nom / den;
        }
        out[0] = loss / (float)BDIM;
    }
}

extern "C" void kernel_launch(void* const* d_in, const int* in_sizes, int n_in,
                              void* d_out, int out_size)
{
    const float* output = (const float*)d_in[0];
    const float* masks  = (const float*)d_in[1];
    const float* thr    = (const float*)d_in[2];

    dim3 ga(ABLK, NBC);          // 288 x 12
    kA<<<ga, ATHR>>>(output, masks, thr);

    dim3 gb(NYC2, NZC2, NBC);    // 6 x 8 x 12 = 576 blocks
    kB<<<gb, BTHR2>>>((float*)d_out);
}